// round 12
// baseline (speedup 1.0000x reference)
#include <cuda_runtime.h>
#include <cuda_fp16.h>
#include <cstdint>

#define BATCH  8
#define SEQ    2048
#define DMODEL 512
#define NHEAD  8
#define DHEAD  64
#define ROWS   (BATCH * SEQ)     // 16384
#define QKVDIM (3 * DMODEL)      // 1536
#define GK     512

// Scratch (allocation-free contract)
__device__ uint32_t g_xnh  [ROWS * DMODEL / 2];   // LN out, fp16 pairs
__device__ uint32_t g_qkvh [ROWS * QKVDIM / 2];   // QKV out, fp16 pairs
__device__ uint32_t g_atth [ROWS * DMODEL / 2];   // attn out, fp16 pairs
__device__ uint32_t g_wqkvh[QKVDIM * DMODEL / 2]; // fp16 weights
__device__ uint32_t g_wprojh[DMODEL * DMODEL / 2];

// ---------------------------------------------------------------------------
// helpers
// ---------------------------------------------------------------------------
__device__ __forceinline__ uint32_t f2h2(float lo, float hi) {
    uint32_t r;
    asm("cvt.rn.f16x2.f32 %0, %1, %2;" : "=r"(r) : "f"(hi), "f"(lo));
    return r;
}

__device__ __forceinline__ uint32_t prmt(uint32_t a, uint32_t b, uint32_t sel) {
    uint32_t d;
    asm("prmt.b32 %0, %1, %2, %3;" : "=r"(d) : "r"(a), "r"(b), "r"(sel));
    return d;
}

__device__ __forceinline__ uint32_t ex2h2(uint32_t x) {
    uint32_t r;
    asm("ex2.approx.f16x2 %0, %1;" : "=r"(r) : "r"(x));
    return r;
}

__device__ __forceinline__ void mma16(float& c0, float& c1, float& c2, float& c3,
                                      uint32_t a0, uint32_t a1, uint32_t a2, uint32_t a3,
                                      uint32_t b0, uint32_t b1) {
    asm volatile(
        "mma.sync.aligned.m16n8k16.row.col.f32.f16.f16.f32 "
        "{%0,%1,%2,%3}, {%4,%5,%6,%7}, {%8,%9}, {%0,%1,%2,%3};"
        : "+f"(c0), "+f"(c1), "+f"(c2), "+f"(c3)
        : "r"(a0), "r"(a1), "r"(a2), "r"(a3), "r"(b0), "r"(b1));
}

// ---------------------------------------------------------------------------
// weight fp32 -> fp16 pairs
// ---------------------------------------------------------------------------
__global__ void cvt_h(const float* __restrict__ in, uint32_t* __restrict__ out, int n2)
{
    int i = blockIdx.x * 256 + threadIdx.x;
    if (i < n2) {
        float2 v = ((const float2*)in)[i];
        out[i] = f2h2(v.x, v.y);
    }
}

// ---------------------------------------------------------------------------
// LayerNorm -> fp16 out
// ---------------------------------------------------------------------------
__global__ __launch_bounds__(128) void ln_kernel(
    const float* __restrict__ x, const float* __restrict__ gamma,
    const float* __restrict__ beta, uint32_t* __restrict__ outh)
{
    int row = blockIdx.x;
    int t   = threadIdx.x;
    const float* xr = x + (size_t)row * DMODEL;
    float4 v = *(const float4*)(xr + t * 4);
    float s  = v.x + v.y + v.z + v.w;
    float ss = v.x * v.x + v.y * v.y + v.z * v.z + v.w * v.w;
#pragma unroll
    for (int m = 16; m; m >>= 1) {
        s  += __shfl_xor_sync(0xffffffffu, s,  m);
        ss += __shfl_xor_sync(0xffffffffu, ss, m);
    }
    __shared__ float red[8];
    if ((t & 31) == 0) { red[t >> 5] = s; red[4 + (t >> 5)] = ss; }
    __syncthreads();
    float tot  = red[0] + red[1] + red[2] + red[3];
    float tot2 = red[4] + red[5] + red[6] + red[7];
    float mu   = tot * (1.0f / DMODEL);
    float var  = tot2 * (1.0f / DMODEL) - mu * mu;
    float rstd = rsqrtf(var + 1e-6f);
    float4 g = *(const float4*)(gamma + t * 4);
    float4 b = *(const float4*)(beta  + t * 4);
    float ox = (v.x - mu) * rstd * g.x + b.x;
    float oy = (v.y - mu) * rstd * g.y + b.y;
    float oz = (v.z - mu) * rstd * g.z + b.z;
    float ow = (v.w - mu) * rstd * g.w + b.w;
    *(uint2*)(outh + (row * DMODEL + t * 4) / 2) =
        make_uint2(f2h2(ox, oy), f2h2(oz, ow));
}

// ---------------------------------------------------------------------------
// fp16 tensor-core GEMM (NT): C[M,N] = A[M,K=512] * B[N,K]^T (+bias)
// CTA tile 256x128x32, 8 warps (4m x 2n), WARP TILE 64x64 -> fragment LDS
// drops to 1.0 word/MMA (was 1.5) and STS/LDG bytes per flop drop 25%.
// Dynamic smem 61.4KB, double-buffered, 1 CTA/SM.
// ---------------------------------------------------------------------------
#define GS 20   // smem row stride in half2 words (16 data + 4 pad)
#define MMTILE_M 256
#define MM_SMEM_BYTES ((2 * 256 * GS + 2 * 128 * GS) * 4)   // 61440

template <bool BIAS, bool HOUT>
__global__ __launch_bounds__(256, 1) void mm_h(
    const __half* __restrict__ A, const __half* __restrict__ Bw,
    const float* __restrict__ bias, void* __restrict__ C, int N)
{
    extern __shared__ uint32_t gsm[];
    uint32_t* Asm = gsm;                 // [2][256][GS]
    uint32_t* Bsm = gsm + 2 * 256 * GS;  // [2][128][GS]

    int t    = threadIdx.x;
    int m0   = blockIdx.y * 256, n0 = blockIdx.x * 128;
    int warp = t >> 5, lane = t & 31, g = lane >> 2, tq = lane & 3;
    int wm   = (warp >> 1) * 64, wn = (warp & 1) * 64;

    int lrow = t >> 2;        // 0..63
    int lk2  = t & 3;         // 8-half group within the 32-k tile
    const __half* Ag = A  + (size_t)(m0 + lrow) * GK + lk2 * 8;
    const __half* Bg = Bw + (size_t)(n0 + lrow) * GK + lk2 * 8;

    float acc[4][8][4];
#pragma unroll
    for (int i = 0; i < 4; i++)
#pragma unroll
        for (int j = 0; j < 8; j++)
#pragma unroll
            for (int r = 0; r < 4; r++) acc[i][j][r] = 0.f;

    uint4 pA[4], pB[2];
#define GLOAD(kt)                                                             \
    do {                                                                      \
        _Pragma("unroll")                                                     \
        for (int j = 0; j < 4; j++)                                           \
            pA[j] = *(const uint4*)(Ag + (size_t)64 * j * GK + (kt) * 32);    \
        _Pragma("unroll")                                                     \
        for (int j = 0; j < 2; j++)                                           \
            pB[j] = *(const uint4*)(Bg + (size_t)64 * j * GK + (kt) * 32);    \
    } while (0)
#define GSTASH(buf)                                                           \
    do {                                                                      \
        _Pragma("unroll")                                                     \
        for (int j = 0; j < 4; j++)                                           \
            *(uint4*)&Asm[(buf) * 256 * GS + (lrow + 64 * j) * GS + lk2 * 4] = pA[j]; \
        _Pragma("unroll")                                                     \
        for (int j = 0; j < 2; j++)                                           \
            *(uint4*)&Bsm[(buf) * 128 * GS + (lrow + 64 * j) * GS + lk2 * 4] = pB[j]; \
    } while (0)

    GLOAD(0);
    GSTASH(0);
    __syncthreads();

    const int NT = GK / 32;   // 16
    for (int kt = 0; kt < NT; kt++) {
        int buf = kt & 1;
        if (kt + 1 < NT) GLOAD(kt + 1);
        const uint32_t* Ab = Asm + buf * 256 * GS;
        const uint32_t* Bb = Bsm + buf * 128 * GS;
#pragma unroll
        for (int ks = 0; ks < 2; ks++) {
            int k0 = ks * 8;
            uint32_t af[4][4], bf[8][2];
#pragma unroll
            for (int mt = 0; mt < 4; mt++) {
                int r = wm + mt * 16 + g;
                af[mt][0] = Ab[r * GS + k0 + tq];
                af[mt][1] = Ab[(r + 8) * GS + k0 + tq];
                af[mt][2] = Ab[r * GS + k0 + tq + 4];
                af[mt][3] = Ab[(r + 8) * GS + k0 + tq + 4];
            }
#pragma unroll
            for (int nt = 0; nt < 8; nt++) {
                int r = wn + nt * 8 + g;
                bf[nt][0] = Bb[r * GS + k0 + tq];
                bf[nt][1] = Bb[r * GS + k0 + tq + 4];
            }
#pragma unroll
            for (int mt = 0; mt < 4; mt++)
#pragma unroll
                for (int nt = 0; nt < 8; nt++)
                    mma16(acc[mt][nt][0], acc[mt][nt][1], acc[mt][nt][2], acc[mt][nt][3],
                          af[mt][0], af[mt][1], af[mt][2], af[mt][3],
                          bf[nt][0], bf[nt][1]);
        }
        if (kt + 1 < NT) GSTASH(buf ^ 1);
        __syncthreads();
    }
#undef GLOAD
#undef GSTASH

#pragma unroll
    for (int mt = 0; mt < 4; mt++) {
#pragma unroll
        for (int nt = 0; nt < 8; nt++) {
            int row = m0 + wm + mt * 16 + g;
            int col = n0 + wn + nt * 8 + 2 * tq;
            if (HOUT) {
                uint32_t* Ch = (uint32_t*)C;
                Ch[((size_t)row * N + col) >> 1] =
                    f2h2(acc[mt][nt][0], acc[mt][nt][1]);
                Ch[((size_t)(row + 8) * N + col) >> 1] =
                    f2h2(acc[mt][nt][2], acc[mt][nt][3]);
            } else {
                float* Cf = (float*)C;
                float b0 = 0.f, b1 = 0.f;
                if (BIAS) { b0 = bias[col]; b1 = bias[col + 1]; }
                *(float2*)(Cf + (size_t)row * N + col) =
                    make_float2(acc[mt][nt][0] + b0, acc[mt][nt][1] + b1);
                *(float2*)(Cf + (size_t)(row + 8) * N + col) =
                    make_float2(acc[mt][nt][2] + b0, acc[mt][nt][3] + b1);
            }
        }
    }
}

// ---------------------------------------------------------------------------
// Flash attention, fp16 mma.sync, exp2-domain softmax, L via ones-column,
// P kept in registers (unchanged from measured-best R11 version).
// ---------------------------------------------------------------------------
#define QS2 36
#define AROWS 256
#define ATTN_SMEM_WORDS (AROWS * QS2 + 2 * 64 * QS2 + 2 * 64 * QS2)

__global__ __launch_bounds__(256, 1) void attn_h(
    const __half* __restrict__ qkv, uint32_t* __restrict__ outh)
{
    extern __shared__ uint32_t smu[];
    uint32_t* QPu = smu;                      // [256][36] Q staging
    uint32_t* Ks  = smu + AROWS * QS2;        // [2][64][36] logical-key-major
    uint32_t* Vs  = Ks + 2 * 64 * QS2;        // [2][64][36] d-major V^T

    int t = threadIdx.x, warp = t >> 5, lane = t & 31, g = lane >> 2, tq = lane & 3;
    int bh = blockIdx.y, b = bh >> 3, h = bh & 7;
    int mb = blockIdx.x * AROWS;
    size_t seq0 = (size_t)b * SEQ;
    const __half* base  = qkv + seq0 * QKVDIM + h * DHEAD;
    const __half* kbase = base + DMODEL;
    const __half* vbase = base + 2 * DMODEL;

    int d4 = t & 15, r0 = t >> 4;

    // Stage Q scaled by 0.125*log2(e) (fp32 scale for precision)
    {
        const float sc = 0.125f * 1.44269504f;
#pragma unroll
        for (int j = 0; j < 16; j++) {
            int row = r0 + 16 * j;
            uint2 q2 = *(const uint2*)(base + (size_t)(mb + row) * QKVDIM + d4 * 4);
            float2 f0 = __half22float2(*(__half2*)&q2.x);
            float2 f1 = __half22float2(*(__half2*)&q2.y);
            *(uint2*)&QPu[row * QS2 + d4 * 2] =
                make_uint2(f2h2(f0.x * sc, f0.y * sc), f2h2(f1.x * sc, f1.y * sc));
        }
    }
    __syncthreads();

    uint32_t* Qw = QPu + warp * 32 * QS2;
    uint32_t qf[2][4][4];
#pragma unroll
    for (int mt = 0; mt < 2; mt++)
#pragma unroll
        for (int ks = 0; ks < 4; ks++) {
            int rA = (mt * 16 + g) * QS2, rB = (mt * 16 + g + 8) * QS2;
            qf[mt][ks][0] = Qw[rA + ks * 8 + tq];
            qf[mt][ks][1] = Qw[rB + ks * 8 + tq];
            qf[mt][ks][2] = Qw[rA + ks * 8 + tq + 4];
            qf[mt][ks][3] = Qw[rB + ks * 8 + tq + 4];
        }

    // oacc[.][8][.] is the L (ones) column
    float oacc[2][9][4];
#pragma unroll
    for (int mt = 0; mt < 2; mt++)
#pragma unroll
        for (int nt = 0; nt < 9; nt++)
#pragma unroll
            for (int r = 0; r < 4; r++) oacc[mt][nt][r] = 0.f;
    float Mm[2][2];
#pragma unroll
    for (int mt = 0; mt < 2; mt++) { Mm[mt][0] = -1e30f; Mm[mt][1] = -1e30f; }

    const int NC = SEQ / 64;
    uint2 kh[4];
    uint32_t vh[8];

#define LDG_CHUNK(c)                                                          \
    do {                                                                      \
        size_t key = (size_t)((c) * 64 + r0);                                 \
        kh[0] = *(const uint2*)(kbase + (key +  0) * QKVDIM + d4 * 4);        \
        kh[1] = *(const uint2*)(kbase + (key + 16) * QKVDIM + d4 * 4);        \
        kh[2] = *(const uint2*)(kbase + (key + 32) * QKVDIM + d4 * 4);        \
        kh[3] = *(const uint2*)(kbase + (key + 48) * QKVDIM + d4 * 4);        \
        uint2 w0 = *(const uint2*)(vbase + (key +  0) * QKVDIM + d4 * 4);     \
        uint2 w1 = *(const uint2*)(vbase + (key + 16) * QKVDIM + d4 * 4);     \
        uint2 w2 = *(const uint2*)(vbase + (key + 32) * QKVDIM + d4 * 4);     \
        uint2 w3 = *(const uint2*)(vbase + (key + 48) * QKVDIM + d4 * 4);     \
        vh[0] = prmt(w0.x, w2.x, 0x5410); vh[1] = prmt(w0.x, w2.x, 0x7632);   \
        vh[2] = prmt(w0.y, w2.y, 0x5410); vh[3] = prmt(w0.y, w2.y, 0x7632);   \
        vh[4] = prmt(w1.x, w3.x, 0x5410); vh[5] = prmt(w1.x, w3.x, 0x7632);   \
        vh[6] = prmt(w1.y, w3.y, 0x5410); vh[7] = prmt(w1.y, w3.y, 0x7632);   \
    } while (0)

#define STS_CHUNK(p)                                                          \
    do {                                                                      \
        uint32_t* kb = Ks + (p) * 64 * QS2;                                   \
        uint32_t* vb = Vs + (p) * 64 * QS2;                                   \
        _Pragma("unroll")                                                     \
        for (int i = 0; i < 4; i++) {                                         \
            int r = r0 + 16 * i;                                              \
            int lam = ((r & 31) << 1) | (r >> 5);                             \
            *(uint2*)&kb[lam * QS2 + d4 * 2] = kh[i];                         \
        }                                                                     \
        _Pragma("unroll")                                                     \
        for (int k = 0; k < 4; k++) {                                         \
            int d = d4 * 4 + k;                                               \
            int sw = ((d >> 3) & 3) << 3;                                     \
            vb[d * QS2 + (r0 ^ sw)]        = vh[k];                           \
            vb[d * QS2 + ((r0 + 16) ^ sw)] = vh[4 + k];                       \
        }                                                                     \
    } while (0)

    LDG_CHUNK(0);
    STS_CHUNK(0);
    LDG_CHUNK(1);
    __syncthreads();

    const uint32_t ONE2 = 0x3C003C00u;   // half2(1.0, 1.0)

    for (int kc = 0; kc < NC; kc++) {
        int p = kc & 1;
        if (kc + 1 < NC) STS_CHUNK(p ^ 1);
        const uint32_t* Kb = Ks + p * 64 * QS2;
        const uint32_t* Vb = Vs + p * 64 * QS2;

        float sacc[2][8][4];
#pragma unroll
        for (int mt = 0; mt < 2; mt++)
#pragma unroll
            for (int nt = 0; nt < 8; nt++)
#pragma unroll
                for (int r = 0; r < 4; r++) sacc[mt][nt][r] = 0.f;

#pragma unroll
        for (int ks = 0; ks < 4; ks++) {
            int k0 = ks * 8;
#pragma unroll
            for (int nt = 0; nt < 8; nt++) {
                int kr = (nt * 8 + g) * QS2;
                uint32_t b0 = Kb[kr + k0 + tq];
                uint32_t b1 = Kb[kr + k0 + tq + 4];
                mma16(sacc[0][nt][0], sacc[0][nt][1], sacc[0][nt][2], sacc[0][nt][3],
                      qf[0][ks][0], qf[0][ks][1], qf[0][ks][2], qf[0][ks][3], b0, b1);
                mma16(sacc[1][nt][0], sacc[1][nt][1], sacc[1][nt][2], sacc[1][nt][3],
                      qf[1][ks][0], qf[1][ks][1], qf[1][ks][2], qf[1][ks][3], b0, b1);
            }
        }

        // Online softmax in log2 domain; P stays in registers as PV A-frags
        uint32_t pa[2][4][4];
#pragma unroll
        for (int mt = 0; mt < 2; mt++) {
            float cm0 = sacc[mt][0][0], cm1 = sacc[mt][0][2];
#pragma unroll
            for (int nt = 0; nt < 8; nt++) {
                cm0 = fmaxf(cm0, fmaxf(sacc[mt][nt][0], sacc[mt][nt][1]));
                cm1 = fmaxf(cm1, fmaxf(sacc[mt][nt][2], sacc[mt][nt][3]));
            }
            cm0 = fmaxf(cm0, __shfl_xor_sync(0xffffffffu, cm0, 1));
            cm0 = fmaxf(cm0, __shfl_xor_sync(0xffffffffu, cm0, 2));
            cm1 = fmaxf(cm1, __shfl_xor_sync(0xffffffffu, cm1, 1));
            cm1 = fmaxf(cm1, __shfl_xor_sync(0xffffffffu, cm1, 2));
            float nM0 = fmaxf(Mm[mt][0], cm0), nM1 = fmaxf(Mm[mt][1], cm1);
            float a0 = exp2f(Mm[mt][0] - nM0), a1 = exp2f(Mm[mt][1] - nM1);
            Mm[mt][0] = nM0; Mm[mt][1] = nM1;

#pragma unroll
            for (int nt = 0; nt < 9; nt++) {
                oacc[mt][nt][0] *= a0; oacc[mt][nt][1] *= a0;
                oacc[mt][nt][2] *= a1; oacc[mt][nt][3] *= a1;
            }
#pragma unroll
            for (int nt = 0; nt < 8; nt++) {
                uint32_t u0 = ex2h2(f2h2(sacc[mt][nt][0] - nM0,
                                         sacc[mt][nt][1] - nM0));
                uint32_t u1 = ex2h2(f2h2(sacc[mt][nt][2] - nM1,
                                         sacc[mt][nt][3] - nM1));
                pa[mt][nt >> 1][(nt & 1) << 1]       = u0;   // a0 / a2
                pa[mt][nt >> 1][((nt & 1) << 1) + 1] = u1;   // a1 / a3
            }
        }

        if (kc + 2 < NC) LDG_CHUNK(kc + 2);

        // O += P @ [V | 1]   (P fragments already in registers)
#pragma unroll
        for (int ks = 0; ks < 4; ks++) {
            int k0 = ks * 8;
#pragma unroll
            for (int nt = 0; nt < 8; nt++) {
                int sw = (nt & 3) << 3;
                int vr = (nt * 8 + g) * QS2;
                uint32_t b0 = Vb[vr + ((k0 + tq) ^ sw)];
                uint32_t b1 = Vb[vr + ((k0 + tq + 4) ^ sw)];
                mma16(oacc[0][nt][0], oacc[0][nt][1], oacc[0][nt][2], oacc[0][nt][3],
                      pa[0][ks][0], pa[0][ks][1], pa[0][ks][2], pa[0][ks][3], b0, b1);
                mma16(oacc[1][nt][0], oacc[1][nt][1], oacc[1][nt][2], oacc[1][nt][3],
                      pa[1][ks][0], pa[1][ks][1], pa[1][ks][2], pa[1][ks][3], b0, b1);
            }
            // L column (ones)
            mma16(oacc[0][8][0], oacc[0][8][1], oacc[0][8][2], oacc[0][8][3],
                  pa[0][ks][0], pa[0][ks][1], pa[0][ks][2], pa[0][ks][3], ONE2, ONE2);
            mma16(oacc[1][8][0], oacc[1][8][1], oacc[1][8][2], oacc[1][8][3],
                  pa[1][ks][0], pa[1][ks][1], pa[1][ks][2], pa[1][ks][3], ONE2, ONE2);
        }
        __syncthreads();
    }
#undef LDG_CHUNK
#undef STS_CHUNK

    // Normalize + pack fp16 pairs
#pragma unroll
    for (int mt = 0; mt < 2; mt++) {
        float i0 = 1.0f / oacc[mt][8][0], i1 = 1.0f / oacc[mt][8][2];
        int row0 = mb + warp * 32 + mt * 16 + g;
#pragma unroll
        for (int nt = 0; nt < 8; nt++) {
            int col = h * DHEAD + nt * 8 + 2 * tq;
            outh[((seq0 + row0) * DMODEL + col) >> 1] =
                f2h2(oacc[mt][nt][0] * i0, oacc[mt][nt][1] * i0);
            outh[((seq0 + row0 + 8) * DMODEL + col) >> 1] =
                f2h2(oacc[mt][nt][2] * i1, oacc[mt][nt][3] * i1);
        }
    }
}

// ---------------------------------------------------------------------------
extern "C" void kernel_launch(void* const* d_in, const int* in_sizes, int n_in,
                              void* d_out, int out_size)
{
    (void)in_sizes; (void)n_in; (void)out_size;
    const float* x      = (const float*)d_in[0];
    const float* w_qkv  = (const float*)d_in[1];
    const float* w_proj = (const float*)d_in[2];
    const float* b_proj = (const float*)d_in[3];
    const float* gamma  = (const float*)d_in[4];
    const float* beta   = (const float*)d_in[5];
    float* out = (float*)d_out;

    uint32_t *xnh, *qkvh, *atth, *wqh, *wph;
    cudaGetSymbolAddress((void**)&xnh,  g_xnh);
    cudaGetSymbolAddress((void**)&qkvh, g_qkvh);
    cudaGetSymbolAddress((void**)&atth, g_atth);
    cudaGetSymbolAddress((void**)&wqh,  g_wqkvh);
    cudaGetSymbolAddress((void**)&wph,  g_wprojh);

    const int SMEM = ATTN_SMEM_WORDS * 4;
    cudaFuncSetAttribute(attn_h,
                         cudaFuncAttributeMaxDynamicSharedMemorySize, SMEM);
    cudaFuncSetAttribute(mm_h<false, true>,
                         cudaFuncAttributeMaxDynamicSharedMemorySize, MM_SMEM_BYTES);
    cudaFuncSetAttribute(mm_h<true, false>,
                         cudaFuncAttributeMaxDynamicSharedMemorySize, MM_SMEM_BYTES);

    cvt_h<<<(QKVDIM * DMODEL / 2 + 255) / 256, 256>>>(w_qkv, wqh, QKVDIM * DMODEL / 2);
    cvt_h<<<(DMODEL * DMODEL / 2 + 255) / 256, 256>>>(w_proj, wph, DMODEL * DMODEL / 2);
    ln_kernel<<<ROWS, 128>>>(x, gamma, beta, xnh);
    mm_h<false, true><<<dim3(QKVDIM / 128, ROWS / MMTILE_M), 256, MM_SMEM_BYTES>>>(
        (const __half*)xnh, (const __half*)wqh, nullptr, qkvh, QKVDIM);
    attn_h<<<dim3(SEQ / AROWS, BATCH * NHEAD), 256, SMEM>>>(
        (const __half*)qkvh, atth);
    mm_h<true, false><<<dim3(DMODEL / 128, ROWS / MMTILE_M), 256, MM_SMEM_BYTES>>>(
        (const __half*)atth, (const __half*)wph, b_proj, out, DMODEL);
}

// round 13
// speedup vs baseline: 1.0359x; 1.0359x over previous
#include <cuda_runtime.h>
#include <cuda_fp16.h>
#include <cstdint>

#define BATCH  8
#define SEQ    2048
#define DMODEL 512
#define NHEAD  8
#define DHEAD  64
#define ROWS   (BATCH * SEQ)     // 16384
#define QKVDIM (3 * DMODEL)      // 1536
#define GK     512

// Scratch (allocation-free contract)
__device__ uint32_t g_xnh  [ROWS * DMODEL / 2];   // LN out, fp16 pairs
__device__ uint32_t g_qkvh [ROWS * QKVDIM / 2];   // QKV out, fp16 pairs
__device__ uint32_t g_atth [ROWS * DMODEL / 2];   // attn out, fp16 pairs
__device__ uint32_t g_wqkvh[QKVDIM * DMODEL / 2]; // fp16 weights
__device__ uint32_t g_wprojh[DMODEL * DMODEL / 2];

// ---------------------------------------------------------------------------
// helpers
// ---------------------------------------------------------------------------
__device__ __forceinline__ uint32_t f2h2(float lo, float hi) {
    uint32_t r;
    asm("cvt.rn.f16x2.f32 %0, %1, %2;" : "=r"(r) : "f"(hi), "f"(lo));
    return r;
}

__device__ __forceinline__ uint32_t prmt(uint32_t a, uint32_t b, uint32_t sel) {
    uint32_t d;
    asm("prmt.b32 %0, %1, %2, %3;" : "=r"(d) : "r"(a), "r"(b), "r"(sel));
    return d;
}

__device__ __forceinline__ uint32_t ex2h2(uint32_t x) {
    uint32_t r;
    asm("ex2.approx.f16x2 %0, %1;" : "=r"(r) : "r"(x));
    return r;
}

__device__ __forceinline__ void mma16(float& c0, float& c1, float& c2, float& c3,
                                      uint32_t a0, uint32_t a1, uint32_t a2, uint32_t a3,
                                      uint32_t b0, uint32_t b1) {
    asm volatile(
        "mma.sync.aligned.m16n8k16.row.col.f32.f16.f16.f32 "
        "{%0,%1,%2,%3}, {%4,%5,%6,%7}, {%8,%9}, {%0,%1,%2,%3};"
        : "+f"(c0), "+f"(c1), "+f"(c2), "+f"(c3)
        : "r"(a0), "r"(a1), "r"(a2), "r"(a3), "r"(b0), "r"(b1));
}

// ---------------------------------------------------------------------------
// weight fp32 -> fp16 pairs
// ---------------------------------------------------------------------------
__global__ void cvt_h(const float* __restrict__ in, uint32_t* __restrict__ out, int n2)
{
    int i = blockIdx.x * 256 + threadIdx.x;
    if (i < n2) {
        float2 v = ((const float2*)in)[i];
        out[i] = f2h2(v.x, v.y);
    }
}

// ---------------------------------------------------------------------------
// LayerNorm -> fp16 out
// ---------------------------------------------------------------------------
__global__ __launch_bounds__(128) void ln_kernel(
    const float* __restrict__ x, const float* __restrict__ gamma,
    const float* __restrict__ beta, uint32_t* __restrict__ outh)
{
    int row = blockIdx.x;
    int t   = threadIdx.x;
    const float* xr = x + (size_t)row * DMODEL;
    float4 v = *(const float4*)(xr + t * 4);
    float s  = v.x + v.y + v.z + v.w;
    float ss = v.x * v.x + v.y * v.y + v.z * v.z + v.w * v.w;
#pragma unroll
    for (int m = 16; m; m >>= 1) {
        s  += __shfl_xor_sync(0xffffffffu, s,  m);
        ss += __shfl_xor_sync(0xffffffffu, ss, m);
    }
    __shared__ float red[8];
    if ((t & 31) == 0) { red[t >> 5] = s; red[4 + (t >> 5)] = ss; }
    __syncthreads();
    float tot  = red[0] + red[1] + red[2] + red[3];
    float tot2 = red[4] + red[5] + red[6] + red[7];
    float mu   = tot * (1.0f / DMODEL);
    float var  = tot2 * (1.0f / DMODEL) - mu * mu;
    float rstd = rsqrtf(var + 1e-6f);
    float4 g = *(const float4*)(gamma + t * 4);
    float4 b = *(const float4*)(beta  + t * 4);
    float ox = (v.x - mu) * rstd * g.x + b.x;
    float oy = (v.y - mu) * rstd * g.y + b.y;
    float oz = (v.z - mu) * rstd * g.z + b.z;
    float ow = (v.w - mu) * rstd * g.w + b.w;
    *(uint2*)(outh + (row * DMODEL + t * 4) / 2) =
        make_uint2(f2h2(ox, oy), f2h2(oz, ow));
}

// ---------------------------------------------------------------------------
// fp16 tensor-core GEMM (NT): C[M,N] = A[M,K=512] * B[N,K]^T (+bias)
// CTA tile 128x128x32 with FOUR warps (2m x 2n), warp tile 64x64 (1.0
// fragment-word/MMA), __launch_bounds__(128,2) -> 2 independent CTAs/SM
// so one CTA's barrier/LDS latency is hidden by the other.
// Dynamic smem 40KB/CTA, double-buffered.
// ---------------------------------------------------------------------------
#define GS 20   // smem row stride in half2 words (16 data + 4 pad)
#define MM_SMEM_BYTES ((2 * 128 * GS + 2 * 128 * GS) * 4)   // 40960

template <bool BIAS, bool HOUT>
__global__ __launch_bounds__(128, 2) void mm_h(
    const __half* __restrict__ A, const __half* __restrict__ Bw,
    const float* __restrict__ bias, void* __restrict__ C, int N)
{
    extern __shared__ uint32_t gsm[];
    uint32_t* Asm = gsm;                 // [2][128][GS]
    uint32_t* Bsm = gsm + 2 * 128 * GS;  // [2][128][GS]

    int t    = threadIdx.x;
    int m0   = blockIdx.y * 128, n0 = blockIdx.x * 128;
    int warp = t >> 5, lane = t & 31, g = lane >> 2, tq = lane & 3;
    int wm   = (warp >> 1) * 64, wn = (warp & 1) * 64;

    int lrow = t >> 2;        // 0..31
    int lk2  = t & 3;         // 8-half group within the 32-k tile
    const __half* Ag = A  + (size_t)(m0 + lrow) * GK + lk2 * 8;
    const __half* Bg = Bw + (size_t)(n0 + lrow) * GK + lk2 * 8;

    float acc[4][8][4];
#pragma unroll
    for (int i = 0; i < 4; i++)
#pragma unroll
        for (int j = 0; j < 8; j++)
#pragma unroll
            for (int r = 0; r < 4; r++) acc[i][j][r] = 0.f;

    uint4 pA[4], pB[4];
#define GLOAD(kt)                                                             \
    do {                                                                      \
        _Pragma("unroll")                                                     \
        for (int j = 0; j < 4; j++) {                                         \
            pA[j] = *(const uint4*)(Ag + (size_t)32 * j * GK + (kt) * 32);    \
            pB[j] = *(const uint4*)(Bg + (size_t)32 * j * GK + (kt) * 32);    \
        }                                                                     \
    } while (0)
#define GSTASH(buf)                                                           \
    do {                                                                      \
        _Pragma("unroll")                                                     \
        for (int j = 0; j < 4; j++) {                                         \
            *(uint4*)&Asm[(buf) * 128 * GS + (lrow + 32 * j) * GS + lk2 * 4] = pA[j]; \
            *(uint4*)&Bsm[(buf) * 128 * GS + (lrow + 32 * j) * GS + lk2 * 4] = pB[j]; \
        }                                                                     \
    } while (0)

    GLOAD(0);
    GSTASH(0);
    __syncthreads();

    const int NT = GK / 32;   // 16
    for (int kt = 0; kt < NT; kt++) {
        int buf = kt & 1;
        if (kt + 1 < NT) GLOAD(kt + 1);
        const uint32_t* Ab = Asm + buf * 128 * GS;
        const uint32_t* Bb = Bsm + buf * 128 * GS;
#pragma unroll
        for (int ks = 0; ks < 2; ks++) {
            int k0 = ks * 8;
            uint32_t af[4][4], bf[8][2];
#pragma unroll
            for (int mt = 0; mt < 4; mt++) {
                int r = wm + mt * 16 + g;
                af[mt][0] = Ab[r * GS + k0 + tq];
                af[mt][1] = Ab[(r + 8) * GS + k0 + tq];
                af[mt][2] = Ab[r * GS + k0 + tq + 4];
                af[mt][3] = Ab[(r + 8) * GS + k0 + tq + 4];
            }
#pragma unroll
            for (int nt = 0; nt < 8; nt++) {
                int r = wn + nt * 8 + g;
                bf[nt][0] = Bb[r * GS + k0 + tq];
                bf[nt][1] = Bb[r * GS + k0 + tq + 4];
            }
#pragma unroll
            for (int mt = 0; mt < 4; mt++)
#pragma unroll
                for (int nt = 0; nt < 8; nt++)
                    mma16(acc[mt][nt][0], acc[mt][nt][1], acc[mt][nt][2], acc[mt][nt][3],
                          af[mt][0], af[mt][1], af[mt][2], af[mt][3],
                          bf[nt][0], bf[nt][1]);
        }
        if (kt + 1 < NT) GSTASH(buf ^ 1);
        __syncthreads();
    }
#undef GLOAD
#undef GSTASH

#pragma unroll
    for (int mt = 0; mt < 4; mt++) {
#pragma unroll
        for (int nt = 0; nt < 8; nt++) {
            int row = m0 + wm + mt * 16 + g;
            int col = n0 + wn + nt * 8 + 2 * tq;
            if (HOUT) {
                uint32_t* Ch = (uint32_t*)C;
                Ch[((size_t)row * N + col) >> 1] =
                    f2h2(acc[mt][nt][0], acc[mt][nt][1]);
                Ch[((size_t)(row + 8) * N + col) >> 1] =
                    f2h2(acc[mt][nt][2], acc[mt][nt][3]);
            } else {
                float* Cf = (float*)C;
                float b0 = 0.f, b1 = 0.f;
                if (BIAS) { b0 = bias[col]; b1 = bias[col + 1]; }
                *(float2*)(Cf + (size_t)row * N + col) =
                    make_float2(acc[mt][nt][0] + b0, acc[mt][nt][1] + b1);
                *(float2*)(Cf + (size_t)(row + 8) * N + col) =
                    make_float2(acc[mt][nt][2] + b0, acc[mt][nt][3] + b1);
            }
        }
    }
}

// ---------------------------------------------------------------------------
// Flash attention, fp16 mma.sync, exp2-domain softmax, L via ones-column,
// P kept in registers (unchanged from measured-best R11 version).
// ---------------------------------------------------------------------------
#define QS2 36
#define AROWS 256
#define ATTN_SMEM_WORDS (AROWS * QS2 + 2 * 64 * QS2 + 2 * 64 * QS2)

__global__ __launch_bounds__(256, 1) void attn_h(
    const __half* __restrict__ qkv, uint32_t* __restrict__ outh)
{
    extern __shared__ uint32_t smu[];
    uint32_t* QPu = smu;                      // [256][36] Q staging
    uint32_t* Ks  = smu + AROWS * QS2;        // [2][64][36] logical-key-major
    uint32_t* Vs  = Ks + 2 * 64 * QS2;        // [2][64][36] d-major V^T

    int t = threadIdx.x, warp = t >> 5, lane = t & 31, g = lane >> 2, tq = lane & 3;
    int bh = blockIdx.y, b = bh >> 3, h = bh & 7;
    int mb = blockIdx.x * AROWS;
    size_t seq0 = (size_t)b * SEQ;
    const __half* base  = qkv + seq0 * QKVDIM + h * DHEAD;
    const __half* kbase = base + DMODEL;
    const __half* vbase = base + 2 * DMODEL;

    int d4 = t & 15, r0 = t >> 4;

    // Stage Q scaled by 0.125*log2(e) (fp32 scale for precision)
    {
        const float sc = 0.125f * 1.44269504f;
#pragma unroll
        for (int j = 0; j < 16; j++) {
            int row = r0 + 16 * j;
            uint2 q2 = *(const uint2*)(base + (size_t)(mb + row) * QKVDIM + d4 * 4);
            float2 f0 = __half22float2(*(__half2*)&q2.x);
            float2 f1 = __half22float2(*(__half2*)&q2.y);
            *(uint2*)&QPu[row * QS2 + d4 * 2] =
                make_uint2(f2h2(f0.x * sc, f0.y * sc), f2h2(f1.x * sc, f1.y * sc));
        }
    }
    __syncthreads();

    uint32_t* Qw = QPu + warp * 32 * QS2;
    uint32_t qf[2][4][4];
#pragma unroll
    for (int mt = 0; mt < 2; mt++)
#pragma unroll
        for (int ks = 0; ks < 4; ks++) {
            int rA = (mt * 16 + g) * QS2, rB = (mt * 16 + g + 8) * QS2;
            qf[mt][ks][0] = Qw[rA + ks * 8 + tq];
            qf[mt][ks][1] = Qw[rB + ks * 8 + tq];
            qf[mt][ks][2] = Qw[rA + ks * 8 + tq + 4];
            qf[mt][ks][3] = Qw[rB + ks * 8 + tq + 4];
        }

    // oacc[.][8][.] is the L (ones) column
    float oacc[2][9][4];
#pragma unroll
    for (int mt = 0; mt < 2; mt++)
#pragma unroll
        for (int nt = 0; nt < 9; nt++)
#pragma unroll
            for (int r = 0; r < 4; r++) oacc[mt][nt][r] = 0.f;
    float Mm[2][2];
#pragma unroll
    for (int mt = 0; mt < 2; mt++) { Mm[mt][0] = -1e30f; Mm[mt][1] = -1e30f; }

    const int NC = SEQ / 64;
    uint2 kh[4];
    uint32_t vh[8];

#define LDG_CHUNK(c)                                                          \
    do {                                                                      \
        size_t key = (size_t)((c) * 64 + r0);                                 \
        kh[0] = *(const uint2*)(kbase + (key +  0) * QKVDIM + d4 * 4);        \
        kh[1] = *(const uint2*)(kbase + (key + 16) * QKVDIM + d4 * 4);        \
        kh[2] = *(const uint2*)(kbase + (key + 32) * QKVDIM + d4 * 4);        \
        kh[3] = *(const uint2*)(kbase + (key + 48) * QKVDIM + d4 * 4);        \
        uint2 w0 = *(const uint2*)(vbase + (key +  0) * QKVDIM + d4 * 4);     \
        uint2 w1 = *(const uint2*)(vbase + (key + 16) * QKVDIM + d4 * 4);     \
        uint2 w2 = *(const uint2*)(vbase + (key + 32) * QKVDIM + d4 * 4);     \
        uint2 w3 = *(const uint2*)(vbase + (key + 48) * QKVDIM + d4 * 4);     \
        vh[0] = prmt(w0.x, w2.x, 0x5410); vh[1] = prmt(w0.x, w2.x, 0x7632);   \
        vh[2] = prmt(w0.y, w2.y, 0x5410); vh[3] = prmt(w0.y, w2.y, 0x7632);   \
        vh[4] = prmt(w1.x, w3.x, 0x5410); vh[5] = prmt(w1.x, w3.x, 0x7632);   \
        vh[6] = prmt(w1.y, w3.y, 0x5410); vh[7] = prmt(w1.y, w3.y, 0x7632);   \
    } while (0)

#define STS_CHUNK(p)                                                          \
    do {                                                                      \
        uint32_t* kb = Ks + (p) * 64 * QS2;                                   \
        uint32_t* vb = Vs + (p) * 64 * QS2;                                   \
        _Pragma("unroll")                                                     \
        for (int i = 0; i < 4; i++) {                                         \
            int r = r0 + 16 * i;                                              \
            int lam = ((r & 31) << 1) | (r >> 5);                             \
            *(uint2*)&kb[lam * QS2 + d4 * 2] = kh[i];                         \
        }                                                                     \
        _Pragma("unroll")                                                     \
        for (int k = 0; k < 4; k++) {                                         \
            int d = d4 * 4 + k;                                               \
            int sw = ((d >> 3) & 3) << 3;                                     \
            vb[d * QS2 + (r0 ^ sw)]        = vh[k];                           \
            vb[d * QS2 + ((r0 + 16) ^ sw)] = vh[4 + k];                       \
        }                                                                     \
    } while (0)

    LDG_CHUNK(0);
    STS_CHUNK(0);
    LDG_CHUNK(1);
    __syncthreads();

    const uint32_t ONE2 = 0x3C003C00u;   // half2(1.0, 1.0)

    for (int kc = 0; kc < NC; kc++) {
        int p = kc & 1;
        if (kc + 1 < NC) STS_CHUNK(p ^ 1);
        const uint32_t* Kb = Ks + p * 64 * QS2;
        const uint32_t* Vb = Vs + p * 64 * QS2;

        float sacc[2][8][4];
#pragma unroll
        for (int mt = 0; mt < 2; mt++)
#pragma unroll
            for (int nt = 0; nt < 8; nt++)
#pragma unroll
                for (int r = 0; r < 4; r++) sacc[mt][nt][r] = 0.f;

#pragma unroll
        for (int ks = 0; ks < 4; ks++) {
            int k0 = ks * 8;
#pragma unroll
            for (int nt = 0; nt < 8; nt++) {
                int kr = (nt * 8 + g) * QS2;
                uint32_t b0 = Kb[kr + k0 + tq];
                uint32_t b1 = Kb[kr + k0 + tq + 4];
                mma16(sacc[0][nt][0], sacc[0][nt][1], sacc[0][nt][2], sacc[0][nt][3],
                      qf[0][ks][0], qf[0][ks][1], qf[0][ks][2], qf[0][ks][3], b0, b1);
                mma16(sacc[1][nt][0], sacc[1][nt][1], sacc[1][nt][2], sacc[1][nt][3],
                      qf[1][ks][0], qf[1][ks][1], qf[1][ks][2], qf[1][ks][3], b0, b1);
            }
        }

        // Online softmax in log2 domain; P stays in registers as PV A-frags
        uint32_t pa[2][4][4];
#pragma unroll
        for (int mt = 0; mt < 2; mt++) {
            float cm0 = sacc[mt][0][0], cm1 = sacc[mt][0][2];
#pragma unroll
            for (int nt = 0; nt < 8; nt++) {
                cm0 = fmaxf(cm0, fmaxf(sacc[mt][nt][0], sacc[mt][nt][1]));
                cm1 = fmaxf(cm1, fmaxf(sacc[mt][nt][2], sacc[mt][nt][3]));
            }
            cm0 = fmaxf(cm0, __shfl_xor_sync(0xffffffffu, cm0, 1));
            cm0 = fmaxf(cm0, __shfl_xor_sync(0xffffffffu, cm0, 2));
            cm1 = fmaxf(cm1, __shfl_xor_sync(0xffffffffu, cm1, 1));
            cm1 = fmaxf(cm1, __shfl_xor_sync(0xffffffffu, cm1, 2));
            float nM0 = fmaxf(Mm[mt][0], cm0), nM1 = fmaxf(Mm[mt][1], cm1);
            float a0 = exp2f(Mm[mt][0] - nM0), a1 = exp2f(Mm[mt][1] - nM1);
            Mm[mt][0] = nM0; Mm[mt][1] = nM1;

#pragma unroll
            for (int nt = 0; nt < 9; nt++) {
                oacc[mt][nt][0] *= a0; oacc[mt][nt][1] *= a0;
                oacc[mt][nt][2] *= a1; oacc[mt][nt][3] *= a1;
            }
#pragma unroll
            for (int nt = 0; nt < 8; nt++) {
                uint32_t u0 = ex2h2(f2h2(sacc[mt][nt][0] - nM0,
                                         sacc[mt][nt][1] - nM0));
                uint32_t u1 = ex2h2(f2h2(sacc[mt][nt][2] - nM1,
                                         sacc[mt][nt][3] - nM1));
                pa[mt][nt >> 1][(nt & 1) << 1]       = u0;   // a0 / a2
                pa[mt][nt >> 1][((nt & 1) << 1) + 1] = u1;   // a1 / a3
            }
        }

        if (kc + 2 < NC) LDG_CHUNK(kc + 2);

        // O += P @ [V | 1]   (P fragments already in registers)
#pragma unroll
        for (int ks = 0; ks < 4; ks++) {
            int k0 = ks * 8;
#pragma unroll
            for (int nt = 0; nt < 8; nt++) {
                int sw = (nt & 3) << 3;
                int vr = (nt * 8 + g) * QS2;
                uint32_t b0 = Vb[vr + ((k0 + tq) ^ sw)];
                uint32_t b1 = Vb[vr + ((k0 + tq + 4) ^ sw)];
                mma16(oacc[0][nt][0], oacc[0][nt][1], oacc[0][nt][2], oacc[0][nt][3],
                      pa[0][ks][0], pa[0][ks][1], pa[0][ks][2], pa[0][ks][3], b0, b1);
                mma16(oacc[1][nt][0], oacc[1][nt][1], oacc[1][nt][2], oacc[1][nt][3],
                      pa[1][ks][0], pa[1][ks][1], pa[1][ks][2], pa[1][ks][3], b0, b1);
            }
            // L column (ones)
            mma16(oacc[0][8][0], oacc[0][8][1], oacc[0][8][2], oacc[0][8][3],
                  pa[0][ks][0], pa[0][ks][1], pa[0][ks][2], pa[0][ks][3], ONE2, ONE2);
            mma16(oacc[1][8][0], oacc[1][8][1], oacc[1][8][2], oacc[1][8][3],
                  pa[1][ks][0], pa[1][ks][1], pa[1][ks][2], pa[1][ks][3], ONE2, ONE2);
        }
        __syncthreads();
    }
#undef LDG_CHUNK
#undef STS_CHUNK

    // Normalize + pack fp16 pairs
#pragma unroll
    for (int mt = 0; mt < 2; mt++) {
        float i0 = 1.0f / oacc[mt][8][0], i1 = 1.0f / oacc[mt][8][2];
        int row0 = mb + warp * 32 + mt * 16 + g;
#pragma unroll
        for (int nt = 0; nt < 8; nt++) {
            int col = h * DHEAD + nt * 8 + 2 * tq;
            outh[((seq0 + row0) * DMODEL + col) >> 1] =
                f2h2(oacc[mt][nt][0] * i0, oacc[mt][nt][1] * i0);
            outh[((seq0 + row0 + 8) * DMODEL + col) >> 1] =
                f2h2(oacc[mt][nt][2] * i1, oacc[mt][nt][3] * i1);
        }
    }
}

// ---------------------------------------------------------------------------
extern "C" void kernel_launch(void* const* d_in, const int* in_sizes, int n_in,
                              void* d_out, int out_size)
{
    (void)in_sizes; (void)n_in; (void)out_size;
    const float* x      = (const float*)d_in[0];
    const float* w_qkv  = (const float*)d_in[1];
    const float* w_proj = (const float*)d_in[2];
    const float* b_proj = (const float*)d_in[3];
    const float* gamma  = (const float*)d_in[4];
    const float* beta   = (const float*)d_in[5];
    float* out = (float*)d_out;

    uint32_t *xnh, *qkvh, *atth, *wqh, *wph;
    cudaGetSymbolAddress((void**)&xnh,  g_xnh);
    cudaGetSymbolAddress((void**)&qkvh, g_qkvh);
    cudaGetSymbolAddress((void**)&atth, g_atth);
    cudaGetSymbolAddress((void**)&wqh,  g_wqkvh);
    cudaGetSymbolAddress((void**)&wph,  g_wprojh);

    const int SMEM = ATTN_SMEM_WORDS * 4;
    cudaFuncSetAttribute(attn_h,
                         cudaFuncAttributeMaxDynamicSharedMemorySize, SMEM);
    cudaFuncSetAttribute(mm_h<false, true>,
                         cudaFuncAttributeMaxDynamicSharedMemorySize, MM_SMEM_BYTES);
    cudaFuncSetAttribute(mm_h<true, false>,
                         cudaFuncAttributeMaxDynamicSharedMemorySize, MM_SMEM_BYTES);

    cvt_h<<<(QKVDIM * DMODEL / 2 + 255) / 256, 256>>>(w_qkv, wqh, QKVDIM * DMODEL / 2);
    cvt_h<<<(DMODEL * DMODEL / 2 + 255) / 256, 256>>>(w_proj, wph, DMODEL * DMODEL / 2);
    ln_kernel<<<ROWS, 128>>>(x, gamma, beta, xnh);
    mm_h<false, true><<<dim3(QKVDIM / 128, ROWS / 128), 128, MM_SMEM_BYTES>>>(
        (const __half*)xnh, (const __half*)wqh, nullptr, qkvh, QKVDIM);
    attn_h<<<dim3(SEQ / AROWS, BATCH * NHEAD), 256, SMEM>>>(
        (const __half*)qkvh, atth);
    mm_h<true, false><<<dim3(DMODEL / 128, ROWS / 128), 128, MM_SMEM_BYTES>>>(
        (const __half*)atth, (const __half*)wph, b_proj, out, DMODEL);
}